// round 9
// baseline (speedup 1.0000x reference)
#include <cuda_runtime.h>
#include <cuda_bf16.h>

#define N_USERS 50000
#define N_ITEMS 50000
#define N_NODES 100000
#define NNZ     1600000
#define EMB     64
#define N_LAYERS 3
#define BATCH   4096
#define REG_L2  1e-5f

#define ROWSTRIDE (EMB * (N_LAYERS + 1))                 // 256
#define CAP 96          // padded edge slots per row (deg ~ Binom(1.6M,1e-5): mean 16, max ~40)

// all_emb: [node][256]; slice k = cols [64k,64k+64). Slice 0 = raw ego,
// slices 1..3 = UNNORMALIZED activations; g_norm = inverse norms.
__device__ float g_all [(size_t)N_NODES * ROWSTRIDE];    // 102.4 MB
__device__ float g_side[(size_t)N_NODES * EMB];          // 25.6 MB
__device__ float g_norm[(size_t)N_LAYERS * N_NODES];     // 1.2 MB
__device__ float g_acc[2];                                // zero at load; re-zeroed by finalize
// bf16 mirror of CURRENT ego slice: gather table for the SpMM
__device__ __nv_bfloat16 g_ego16[(size_t)N_NODES * EMB]; // 12.8 MB

// Padded edge table (replaces CSR + its 4-kernel build chain)
__device__ int  g_deg[N_NODES];                           // zero at load; re-zeroed by loss
__device__ int2 g_pad[(size_t)N_NODES * CAP];             // 76.8 MB {col, val bits}

__device__ __forceinline__ float4 bf16x4_to_f4(uint2 r) {
    __nv_bfloat162 lo = *(__nv_bfloat162*)&r.x;
    __nv_bfloat162 hi = *(__nv_bfloat162*)&r.y;
    float2 a = __bfloat1622float2(lo), b = __bfloat1622float2(hi);
    return make_float4(a.x, a.y, b.x, b.y);
}

// ---- packed fp32x2 helpers (sm_103a) ----
__device__ __forceinline__ unsigned long long splat2(float f) {
    unsigned long long d;
    unsigned int b = __float_as_uint(f);
    asm("mov.b64 %0, {%1, %1};" : "=l"(d) : "r"(b));
    return d;
}
#define FMA2(acc, a, b) \
    asm("fma.rn.f32x2 %0, %1, %2, %0;" : "+l"(acc) : "l"(a), "l"(b))
__device__ __forceinline__ float2 unpack2(unsigned long long v) {
    unsigned int lo, hi;
    asm("mov.b64 {%0, %1}, %2;" : "=r"(lo), "=r"(hi) : "l"(v));
    return make_float2(__uint_as_float(lo), __uint_as_float(hi));
}

// ---------------------------------------------------------------------------
__global__ void init_kernel(const float* __restrict__ ue, const float* __restrict__ ie) {
    int t = blockIdx.x * 256 + threadIdx.x;              // N_NODES*16 threads
    int node = t >> 4, q = t & 15;
    const float* src = (node < N_USERS) ? (ue + (size_t)node * EMB)
                                        : (ie + (size_t)(node - N_USERS) * EMB);
    float4 v = *(const float4*)(src + q * 4);
    *(float4*)(g_all + (size_t)node * ROWSTRIDE + q * 4) = v;
    __nv_bfloat162* b = (__nv_bfloat162*)(g_ego16 + (size_t)node * EMB + q * 4);
    b[0] = __floats2bfloat162_rn(v.x, v.y);
    b[1] = __floats2bfloat162_rn(v.z, v.w);
}

// ---------------------------------------------------------------------------
// Padded-table build: one pass, no scans. g_deg doubles as slot counter.
// ---------------------------------------------------------------------------
__global__ void scatter_kernel(const int* __restrict__ row,
                               const int* __restrict__ col,
                               const float* __restrict__ val) {
    int t = blockIdx.x * 256 + threadIdx.x;
    if (t >= NNZ) return;
    int r = __ldg(row + t);
    int slot = atomicAdd(&g_deg[r], 1);
    if (slot < CAP)
        g_pad[(size_t)r * CAP + slot] = make_int2(__ldg(col + t),
                                                  __float_as_int(__ldg(val + t)));
}

// ---------------------------------------------------------------------------
// SpMM: one warp per row, half-warp per edge, padded rows (contiguous).
// ---------------------------------------------------------------------------
__global__ void __launch_bounds__(256) spmm_kernel() {
    int gt = blockIdx.x * 256 + threadIdx.x;
    int row = gt >> 5, lane = gt & 31;
    if (row >= N_NODES) return;
    int half = lane >> 4;
    int sub  = lane & 15;

    int deg = __ldg(&g_deg[row]);                        // broadcast
    if (deg > CAP) deg = CAP;
    const int2* edges = g_pad + (size_t)row * CAP;
    float4 acc = make_float4(0.f, 0.f, 0.f, 0.f);

    int e = 0;
    for (; e + 8 <= deg; e += 8) {
        int2 c0 = __ldg(edges + e     + half);
        int2 c1 = __ldg(edges + e + 2 + half);
        int2 c2 = __ldg(edges + e + 4 + half);
        int2 c3 = __ldg(edges + e + 6 + half);
        uint2 r0 = __ldg((const uint2*)(g_ego16 + (size_t)c0.x * EMB) + sub);
        uint2 r1 = __ldg((const uint2*)(g_ego16 + (size_t)c1.x * EMB) + sub);
        uint2 r2 = __ldg((const uint2*)(g_ego16 + (size_t)c2.x * EMB) + sub);
        uint2 r3 = __ldg((const uint2*)(g_ego16 + (size_t)c3.x * EMB) + sub);
        float4 a0 = bf16x4_to_f4(r0), a1 = bf16x4_to_f4(r1);
        float4 a2 = bf16x4_to_f4(r2), a3 = bf16x4_to_f4(r3);
        float v0 = __int_as_float(c0.y), v1 = __int_as_float(c1.y);
        float v2 = __int_as_float(c2.y), v3 = __int_as_float(c3.y);
        acc.x += v0 * a0.x + v1 * a1.x + v2 * a2.x + v3 * a3.x;
        acc.y += v0 * a0.y + v1 * a1.y + v2 * a2.y + v3 * a3.y;
        acc.z += v0 * a0.z + v1 * a1.z + v2 * a2.z + v3 * a3.z;
        acc.w += v0 * a0.w + v1 * a1.w + v2 * a2.w + v3 * a3.w;
    }
    for (; e + 2 <= deg; e += 2) {
        int2 c = __ldg(edges + e + half);
        uint2 r = __ldg((const uint2*)(g_ego16 + (size_t)c.x * EMB) + sub);
        float4 a = bf16x4_to_f4(r);
        float v = __int_as_float(c.y);
        acc.x += v * a.x; acc.y += v * a.y; acc.z += v * a.z; acc.w += v * a.w;
    }
    if (e < deg && half == 0) {
        int2 c = __ldg(edges + e);
        uint2 r = __ldg((const uint2*)(g_ego16 + (size_t)c.x * EMB) + sub);
        float4 a = bf16x4_to_f4(r);
        float v = __int_as_float(c.y);
        acc.x += v * a.x; acc.y += v * a.y; acc.z += v * a.z; acc.w += v * a.w;
    }

    acc.x += __shfl_xor_sync(0xffffffffu, acc.x, 16);
    acc.y += __shfl_xor_sync(0xffffffffu, acc.y, 16);
    acc.z += __shfl_xor_sync(0xffffffffu, acc.z, 16);
    acc.w += __shfl_xor_sync(0xffffffffu, acc.w, 16);
    if (half == 0)
        *(float4*)(g_side + (size_t)row * EMB + sub * 4) = acc;
}

// ---------------------------------------------------------------------------
// Transform with packed fp32x2 FMAs; 8 row-pairs (16 rows) per warp to
// amortize the W smem reads (the L1-crossbar bottleneck) over 2x rows.
// smem: W 32KB + bias 256B + X staging 8KB/warp * 8 = ~96.5KB -> 2 blocks/SM.
// ---------------------------------------------------------------------------
#define NRP 8                                             // row-pairs per warp
#define TR_SMEM (2048 * 16 + 64 * 4 + 256 * (NRP * 64 * 16))
// = 32768 + 256 + 65536 ... expressed explicitly below:
#undef TR_SMEM
#define TR_SMEM (2048 * 16 + 64 * 4 + 8 * NRP * 64 * 16)

__global__ void __launch_bounds__(256, 2) transform_kernel(
        const float* __restrict__ Wg, const float* __restrict__ bg,
        const float* __restrict__ Wb, const float* __restrict__ bb, int k) {
    extern __shared__ float sh[];
    float4* shW4 = (float4*)sh;                   // [j*32+lane]
    float*  shB  = sh + 2048 * 4;
    float4* shXp = (float4*)(shB + 64);           // [warp][rp*64 + j]

    int tid = threadIdx.x;
    const float* Wg_k = Wg + k * 4096;
    const float* Wb_k = Wb + k * 4096;
    #pragma unroll
    for (int idx = tid; idx < 2048; idx += 256) {
        int j = idx >> 5, l = idx & 31;
        float2 g = *(const float2*)(Wg_k + j * 64 + l * 2);
        float2 b = *(const float2*)(Wb_k + j * 64 + l * 2);
        shW4[idx] = make_float4(g.x, g.y, b.x, b.y);
    }
    if (tid < 64) shB[tid] = bg[k * 64 + tid] + bb[k * 64 + tid];
    __syncthreads();

    int warp = tid >> 5, lane = tid & 31;
    int rowbase = (blockIdx.x * 8 + warp) * (2 * NRP);
    float4* shXw = shXp + warp * (NRP * 64);
    const float* ego = g_all + k * EMB;

    #pragma unroll
    for (int rp = 0; rp < NRP; rp++) {
        float2 x1e = make_float2(0.f, 0.f), x2e = x1e;
        float2 x1o = x1e, x2o = x1e;
        int re = rowbase + 2 * rp, ro = re + 1;
        if (re < N_NODES) {
            float2 s = *(const float2*)(g_side + (size_t)re * EMB + lane * 2);
            float2 e = *(const float2*)(ego + (size_t)re * ROWSTRIDE + lane * 2);
            x1e = s;
            x2e = make_float2(e.x * (s.x - e.x), e.y * (s.y - e.y));
        }
        if (ro < N_NODES) {
            float2 s = *(const float2*)(g_side + (size_t)ro * EMB + lane * 2);
            float2 e = *(const float2*)(ego + (size_t)ro * ROWSTRIDE + lane * 2);
            x1o = s;
            x2o = make_float2(e.x * (s.x - e.x), e.y * (s.y - e.y));
        }
        shXw[rp * 64 + 2 * lane]     = make_float4(x1e.x, x1o.x, x2e.x, x2o.x);
        shXw[rp * 64 + 2 * lane + 1] = make_float4(x1e.y, x1o.y, x2e.y, x2o.y);
    }
    __syncwarp();

    unsigned long long acc0[NRP], acc1[NRP];
    {
        unsigned long long b0 = splat2(shB[2 * lane]);
        unsigned long long b1 = splat2(shB[2 * lane + 1]);
        #pragma unroll
        for (int rp = 0; rp < NRP; rp++) { acc0[rp] = b0; acc1[rp] = b1; }
    }

    const ulonglong2* shXw2 = (const ulonglong2*)shXw;
    #pragma unroll 2
    for (int j = 0; j < 64; j++) {
        float4 w = shW4[j * 32 + lane];
        unsigned long long wg0 = splat2(w.x), wg1 = splat2(w.y);
        unsigned long long wb0 = splat2(w.z), wb1 = splat2(w.w);
        #pragma unroll
        for (int rp = 0; rp < NRP; rp++) {
            ulonglong2 xp = shXw2[rp * 64 + j];
            FMA2(acc0[rp], xp.x, wg0);
            FMA2(acc0[rp], xp.y, wb0);
            FMA2(acc1[rp], xp.x, wg1);
            FMA2(acc1[rp], xp.y, wb1);
        }
    }

    #pragma unroll
    for (int rp = 0; rp < NRP; rp++) {
        float2 c0 = unpack2(acc0[rp]);
        float2 c1 = unpack2(acc1[rp]);
        #pragma unroll
        for (int odd = 0; odd < 2; odd++) {
            int row = rowbase + 2 * rp + odd;
            float v0 = odd ? c0.y : c0.x;
            float v1 = odd ? c1.y : c1.x;
            v0 = (v0 >= 0.f) ? v0 : 0.01f * v0;
            v1 = (v1 >= 0.f) ? v1 : 0.01f * v1;
            float p = v0 * v0 + v1 * v1;
            #pragma unroll
            for (int o = 16; o; o >>= 1) p += __shfl_xor_sync(0xffffffffu, p, o);
            float inv = 1.f / fmaxf(sqrtf(p), 1e-12f);
            if (row < N_NODES) {
                *(float2*)(g_all + (size_t)row * ROWSTRIDE + (k + 1) * EMB + lane * 2)
                    = make_float2(v0, v1);
                if (k < N_LAYERS - 1)
                    *(__nv_bfloat162*)(g_ego16 + (size_t)row * EMB + lane * 2)
                        = __floats2bfloat162_rn(v0, v1);
                if (lane == 0) g_norm[(size_t)k * N_NODES + row] = inv;
            }
        }
    }
}

// ---------------------------------------------------------------------------
// BPR loss: one warp per batch element; also re-zeroes g_deg for next replay.
// ---------------------------------------------------------------------------
__global__ void loss_kernel(const int* __restrict__ u,
                            const int* __restrict__ ii,
                            const int* __restrict__ jj) {
    int t = blockIdx.x * 128 + threadIdx.x;               // 131072 threads
    if (t < N_NODES) g_deg[t] = 0;                        // reset edge counters

    int warp = threadIdx.x >> 5, lane = threadIdx.x & 31;
    int b = blockIdx.x * 4 + warp;
    int un = u[b], pn = N_USERS + ii[b], nn = N_USERS + jj[b];
    const float* ur = g_all + (size_t)un * ROWSTRIDE;
    const float* pr = g_all + (size_t)pn * ROWSTRIDE;
    const float* nr = g_all + (size_t)nn * ROWSTRIDE;

    float iu[4], ip[4], in_[4];
    iu[0] = ip[0] = in_[0] = 1.f;
    #pragma unroll
    for (int s = 1; s < 4; s++) {
        iu[s]  = __ldg(&g_norm[(size_t)(s - 1) * N_NODES + un]);
        ip[s]  = __ldg(&g_norm[(size_t)(s - 1) * N_NODES + pn]);
        in_[s] = __ldg(&g_norm[(size_t)(s - 1) * N_NODES + nn]);
    }

    float dui = 0.f, duj = 0.f, l2 = 0.f;
    #pragma unroll
    for (int s = 0; s < 4; s++) {
        float2 uv = *(const float2*)(ur + s * EMB + lane * 2);
        float2 pv = *(const float2*)(pr + s * EMB + lane * 2);
        float2 nv = *(const float2*)(nr + s * EMB + lane * 2);
        uv.x *= iu[s];  uv.y *= iu[s];
        pv.x *= ip[s];  pv.y *= ip[s];
        nv.x *= in_[s]; nv.y *= in_[s];
        dui += uv.x * pv.x + uv.y * pv.y;
        duj += uv.x * nv.x + uv.y * nv.y;
        l2  += uv.x * uv.x + uv.y * uv.y
             + pv.x * pv.x + pv.y * pv.y
             + nv.x * nv.x + nv.y * nv.y;
    }
    #pragma unroll
    for (int o = 16; o; o >>= 1) {
        dui += __shfl_xor_sync(0xffffffffu, dui, o);
        duj += __shfl_xor_sync(0xffffffffu, duj, o);
        l2  += __shfl_xor_sync(0xffffffffu, l2,  o);
    }
    if (lane == 0) {
        float diff = dui - duj;
        float lp = fminf(diff, 0.f) - log1pf(expf(-fabsf(diff)));
        atomicAdd(&g_acc[0], lp);
        atomicAdd(&g_acc[1], 0.5f * l2);
    }
}

__global__ void finalize_kernel(float* out) {
    out[0] = -g_acc[0] / (float)BATCH + REG_L2 * (g_acc[1] / (float)BATCH);
    g_acc[0] = 0.f;
    g_acc[1] = 0.f;
}

// ---------------------------------------------------------------------------
extern "C" void kernel_launch(void* const* d_in, const int* in_sizes, int n_in,
                              void* d_out, int out_size) {
    const float* user_emb = (const float*)d_in[0];
    const float* item_emb = (const float*)d_in[1];
    const float* W_gc     = (const float*)d_in[2];
    const float* b_gc     = (const float*)d_in[3];
    const float* W_bi     = (const float*)d_in[4];
    const float* b_bi     = (const float*)d_in[5];
    const float* adj_val  = (const float*)d_in[6];
    const int*   adj_row  = (const int*)d_in[7];
    const int*   adj_col  = (const int*)d_in[8];
    const int*   u        = (const int*)d_in[9];
    const int*   i        = (const int*)d_in[10];
    const int*   j        = (const int*)d_in[11];
    float* out = (float*)d_out;

    static bool configured = false;
    if (!configured) {
        configured = true;
        cudaFuncSetAttribute(transform_kernel,
                             cudaFuncAttributeMaxDynamicSharedMemorySize, TR_SMEM);
    }

    init_kernel<<<(N_NODES * 16) / 256, 256>>>(user_emb, item_emb);
    scatter_kernel<<<(NNZ + 255) / 256, 256>>>(adj_row, adj_col, adj_val);

    const int rows_per_block = 8 * 2 * NRP;               // 128
    for (int k = 0; k < N_LAYERS; k++) {
        spmm_kernel<<<(N_NODES * 32 + 255) / 256, 256>>>();
        transform_kernel<<<(N_NODES + rows_per_block - 1) / rows_per_block,
                           256, TR_SMEM>>>(W_gc, b_gc, W_bi, b_bi, k);
    }

    loss_kernel<<<BATCH / 4, 128>>>(u, i, j);
    finalize_kernel<<<1, 1>>>(out);
}

// round 10
// speedup vs baseline: 1.0799x; 1.0799x over previous
#include <cuda_runtime.h>
#include <cuda_bf16.h>

#define N_USERS 50000
#define N_ITEMS 50000
#define N_NODES 100000
#define NNZ     1600000
#define EMB     64
#define N_LAYERS 3
#define BATCH   4096
#define REG_L2  1e-5f

#define ROWSTRIDE (EMB * (N_LAYERS + 1))                 // 256
#define CAP 96          // padded edge slots per row (deg ~ Binom(1.6M,1e-5): mean 16, max ~40)

__device__ float g_all [(size_t)N_NODES * ROWSTRIDE];    // 102.4 MB
__device__ float g_side[(size_t)N_NODES * EMB];          // 25.6 MB
__device__ float g_norm[(size_t)N_LAYERS * N_NODES];     // 1.2 MB
__device__ float g_acc[2];                                // zero at load; re-zeroed by finalize
__device__ __nv_bfloat16 g_ego16[(size_t)N_NODES * EMB]; // 12.8 MB bf16 gather mirror

__device__ int  g_deg[N_NODES];                           // zero at load; re-zeroed by loss
__device__ int2 g_pad[(size_t)N_NODES * CAP];             // 76.8 MB {col, val bits}

__device__ __forceinline__ float4 bf16x4_to_f4(uint2 r) {
    __nv_bfloat162 lo = *(__nv_bfloat162*)&r.x;
    __nv_bfloat162 hi = *(__nv_bfloat162*)&r.y;
    float2 a = __bfloat1622float2(lo), b = __bfloat1622float2(hi);
    return make_float4(a.x, a.y, b.x, b.y);
}

// ---- packed fp32x2 helpers (sm_103a) ----
__device__ __forceinline__ unsigned long long splat2(float f) {
    unsigned long long d;
    unsigned int b = __float_as_uint(f);
    asm("mov.b64 %0, {%1, %1};" : "=l"(d) : "r"(b));
    return d;
}
#define FMA2(acc, a, b) \
    asm("fma.rn.f32x2 %0, %1, %2, %0;" : "+l"(acc) : "l"(a), "l"(b))
__device__ __forceinline__ float2 unpack2(unsigned long long v) {
    unsigned int lo, hi;
    asm("mov.b64 {%0, %1}, %2;" : "=r"(lo), "=r"(hi) : "l"(v));
    return make_float2(__uint_as_float(lo), __uint_as_float(hi));
}

// ---------------------------------------------------------------------------
__global__ void init_kernel(const float* __restrict__ ue, const float* __restrict__ ie) {
    int t = blockIdx.x * 256 + threadIdx.x;              // N_NODES*16 threads
    int node = t >> 4, q = t & 15;
    const float* src = (node < N_USERS) ? (ue + (size_t)node * EMB)
                                        : (ie + (size_t)(node - N_USERS) * EMB);
    float4 v = *(const float4*)(src + q * 4);
    *(float4*)(g_all + (size_t)node * ROWSTRIDE + q * 4) = v;
    __nv_bfloat162* b = (__nv_bfloat162*)(g_ego16 + (size_t)node * EMB + q * 4);
    b[0] = __floats2bfloat162_rn(v.x, v.y);
    b[1] = __floats2bfloat162_rn(v.z, v.w);
}

// ---------------------------------------------------------------------------
__global__ void scatter_kernel(const int* __restrict__ row,
                               const int* __restrict__ col,
                               const float* __restrict__ val) {
    int t = blockIdx.x * 256 + threadIdx.x;
    if (t >= NNZ) return;
    int r = __ldg(row + t);
    int slot = atomicAdd(&g_deg[r], 1);
    if (slot < CAP)
        g_pad[(size_t)r * CAP + slot] = make_int2(__ldg(col + t),
                                                  __float_as_int(__ldg(val + t)));
}

// ---------------------------------------------------------------------------
// SpMM: one warp per row, half-warp per edge, padded rows (proven config).
// ---------------------------------------------------------------------------
__global__ void __launch_bounds__(256) spmm_kernel() {
    int gt = blockIdx.x * 256 + threadIdx.x;
    int row = gt >> 5, lane = gt & 31;
    if (row >= N_NODES) return;
    int half = lane >> 4;
    int sub  = lane & 15;

    int deg = __ldg(&g_deg[row]);
    if (deg > CAP) deg = CAP;
    const int2* edges = g_pad + (size_t)row * CAP;
    float4 acc = make_float4(0.f, 0.f, 0.f, 0.f);

    int e = 0;
    for (; e + 8 <= deg; e += 8) {
        int2 c0 = __ldg(edges + e     + half);
        int2 c1 = __ldg(edges + e + 2 + half);
        int2 c2 = __ldg(edges + e + 4 + half);
        int2 c3 = __ldg(edges + e + 6 + half);
        uint2 r0 = __ldg((const uint2*)(g_ego16 + (size_t)c0.x * EMB) + sub);
        uint2 r1 = __ldg((const uint2*)(g_ego16 + (size_t)c1.x * EMB) + sub);
        uint2 r2 = __ldg((const uint2*)(g_ego16 + (size_t)c2.x * EMB) + sub);
        uint2 r3 = __ldg((const uint2*)(g_ego16 + (size_t)c3.x * EMB) + sub);
        float4 a0 = bf16x4_to_f4(r0), a1 = bf16x4_to_f4(r1);
        float4 a2 = bf16x4_to_f4(r2), a3 = bf16x4_to_f4(r3);
        float v0 = __int_as_float(c0.y), v1 = __int_as_float(c1.y);
        float v2 = __int_as_float(c2.y), v3 = __int_as_float(c3.y);
        acc.x += v0 * a0.x + v1 * a1.x + v2 * a2.x + v3 * a3.x;
        acc.y += v0 * a0.y + v1 * a1.y + v2 * a2.y + v3 * a3.y;
        acc.z += v0 * a0.z + v1 * a1.z + v2 * a2.z + v3 * a3.z;
        acc.w += v0 * a0.w + v1 * a1.w + v2 * a2.w + v3 * a3.w;
    }
    for (; e + 2 <= deg; e += 2) {
        int2 c = __ldg(edges + e + half);
        uint2 r = __ldg((const uint2*)(g_ego16 + (size_t)c.x * EMB) + sub);
        float4 a = bf16x4_to_f4(r);
        float v = __int_as_float(c.y);
        acc.x += v * a.x; acc.y += v * a.y; acc.z += v * a.z; acc.w += v * a.w;
    }
    if (e < deg && half == 0) {
        int2 c = __ldg(edges + e);
        uint2 r = __ldg((const uint2*)(g_ego16 + (size_t)c.x * EMB) + sub);
        float4 a = bf16x4_to_f4(r);
        float v = __int_as_float(c.y);
        acc.x += v * a.x; acc.y += v * a.y; acc.z += v * a.z; acc.w += v * a.w;
    }

    acc.x += __shfl_xor_sync(0xffffffffu, acc.x, 16);
    acc.y += __shfl_xor_sync(0xffffffffu, acc.y, 16);
    acc.z += __shfl_xor_sync(0xffffffffu, acc.z, 16);
    acc.w += __shfl_xor_sync(0xffffffffu, acc.w, 16);
    if (half == 0)
        *(float4*)(g_side + (size_t)row * EMB + sub * 4) = acc;
}

// ---------------------------------------------------------------------------
// Transform: persistent grid (3 blocks/SM), NRP=4, software-pipelined j-loop.
// smem: W 32KB + bias 256B + X 4KB/warp*8 = 64.75KB -> 3 blocks/SM = 24 warps.
// ---------------------------------------------------------------------------
#define NRP 4
#define TR_SMEM (2048 * 16 + 64 * 4 + 8 * NRP * 64 * 16)   // 64.75 KB
#define TR_GRID (148 * 3)                                   // persistent, 3/SM
#define TILE_ROWS (8 * 2 * NRP)                             // 64 rows per block-tile
#define N_TILES ((N_NODES + TILE_ROWS - 1) / TILE_ROWS)     // 1563

__global__ void __launch_bounds__(256, 3) transform_kernel(
        const float* __restrict__ Wg, const float* __restrict__ bg,
        const float* __restrict__ Wb, const float* __restrict__ bb, int k) {
    extern __shared__ float sh[];
    float4* shW4 = (float4*)sh;                   // [j*32+lane]
    float*  shB  = sh + 2048 * 4;
    float4* shXp = (float4*)(shB + 64);           // [warp][rp*64 + j]

    int tid = threadIdx.x;
    const float* Wg_k = Wg + k * 4096;
    const float* Wb_k = Wb + k * 4096;
    #pragma unroll
    for (int idx = tid; idx < 2048; idx += 256) {
        int j = idx >> 5, l = idx & 31;
        float2 g = *(const float2*)(Wg_k + j * 64 + l * 2);
        float2 b = *(const float2*)(Wb_k + j * 64 + l * 2);
        shW4[idx] = make_float4(g.x, g.y, b.x, b.y);
    }
    if (tid < 64) shB[tid] = bg[k * 64 + tid] + bb[k * 64 + tid];
    __syncthreads();

    int warp = tid >> 5, lane = tid & 31;
    float4* shXw = shXp + warp * (NRP * 64);
    const ulonglong2* shXw2 = (const ulonglong2*)shXw;
    const float* ego = g_all + k * EMB;
    unsigned long long bias0 = splat2(shB[2 * lane]);
    unsigned long long bias1 = splat2(shB[2 * lane + 1]);

    for (int tile = blockIdx.x; tile < N_TILES; tile += TR_GRID) {
        int rowbase = tile * TILE_ROWS + warp * (2 * NRP);

        // Stage x1/x2 for 8 rows (4 row-pairs)
        #pragma unroll
        for (int rp = 0; rp < NRP; rp++) {
            float2 x1e = make_float2(0.f, 0.f), x2e = x1e;
            float2 x1o = x1e, x2o = x1e;
            int re = rowbase + 2 * rp, ro = re + 1;
            if (re < N_NODES) {
                float2 s = *(const float2*)(g_side + (size_t)re * EMB + lane * 2);
                float2 e = *(const float2*)(ego + (size_t)re * ROWSTRIDE + lane * 2);
                x1e = s;
                x2e = make_float2(e.x * (s.x - e.x), e.y * (s.y - e.y));
            }
            if (ro < N_NODES) {
                float2 s = *(const float2*)(g_side + (size_t)ro * EMB + lane * 2);
                float2 e = *(const float2*)(ego + (size_t)ro * ROWSTRIDE + lane * 2);
                x1o = s;
                x2o = make_float2(e.x * (s.x - e.x), e.y * (s.y - e.y));
            }
            shXw[rp * 64 + 2 * lane]     = make_float4(x1e.x, x1o.x, x2e.x, x2o.x);
            shXw[rp * 64 + 2 * lane + 1] = make_float4(x1e.y, x1o.y, x2e.y, x2o.y);
        }
        __syncwarp();

        unsigned long long acc0[NRP], acc1[NRP];
        #pragma unroll
        for (int rp = 0; rp < NRP; rp++) { acc0[rp] = bias0; acc1[rp] = bias1; }

        // Software-pipelined j-loop: load j+1 while computing j.
        float4 wc = shW4[lane];
        ulonglong2 xc0 = shXw2[0],       xc1 = shXw2[64];
        ulonglong2 xc2 = shXw2[128],     xc3 = shXw2[192];

        #pragma unroll 4
        for (int j = 0; j < 63; j++) {
            float4 wn = shW4[(j + 1) * 32 + lane];
            ulonglong2 xn0 = shXw2[j + 1],       xn1 = shXw2[64 + j + 1];
            ulonglong2 xn2 = shXw2[128 + j + 1], xn3 = shXw2[192 + j + 1];

            unsigned long long wg0 = splat2(wc.x), wg1 = splat2(wc.y);
            unsigned long long wb0 = splat2(wc.z), wb1 = splat2(wc.w);
            FMA2(acc0[0], xc0.x, wg0); FMA2(acc0[0], xc0.y, wb0);
            FMA2(acc1[0], xc0.x, wg1); FMA2(acc1[0], xc0.y, wb1);
            FMA2(acc0[1], xc1.x, wg0); FMA2(acc0[1], xc1.y, wb0);
            FMA2(acc1[1], xc1.x, wg1); FMA2(acc1[1], xc1.y, wb1);
            FMA2(acc0[2], xc2.x, wg0); FMA2(acc0[2], xc2.y, wb0);
            FMA2(acc1[2], xc2.x, wg1); FMA2(acc1[2], xc2.y, wb1);
            FMA2(acc0[3], xc3.x, wg0); FMA2(acc0[3], xc3.y, wb0);
            FMA2(acc1[3], xc3.x, wg1); FMA2(acc1[3], xc3.y, wb1);

            wc = wn; xc0 = xn0; xc1 = xn1; xc2 = xn2; xc3 = xn3;
        }
        {   // final j = 63
            unsigned long long wg0 = splat2(wc.x), wg1 = splat2(wc.y);
            unsigned long long wb0 = splat2(wc.z), wb1 = splat2(wc.w);
            FMA2(acc0[0], xc0.x, wg0); FMA2(acc0[0], xc0.y, wb0);
            FMA2(acc1[0], xc0.x, wg1); FMA2(acc1[0], xc0.y, wb1);
            FMA2(acc0[1], xc1.x, wg0); FMA2(acc0[1], xc1.y, wb0);
            FMA2(acc1[1], xc1.x, wg1); FMA2(acc1[1], xc1.y, wb1);
            FMA2(acc0[2], xc2.x, wg0); FMA2(acc0[2], xc2.y, wb0);
            FMA2(acc1[2], xc2.x, wg1); FMA2(acc1[2], xc2.y, wb1);
            FMA2(acc0[3], xc3.x, wg0); FMA2(acc0[3], xc3.y, wb0);
            FMA2(acc1[3], xc3.x, wg1); FMA2(acc1[3], xc3.y, wb1);
        }

        // Epilogue
        #pragma unroll
        for (int rp = 0; rp < NRP; rp++) {
            float2 c0 = unpack2(acc0[rp]);
            float2 c1 = unpack2(acc1[rp]);
            #pragma unroll
            for (int odd = 0; odd < 2; odd++) {
                int row = rowbase + 2 * rp + odd;
                float v0 = odd ? c0.y : c0.x;
                float v1 = odd ? c1.y : c1.x;
                v0 = (v0 >= 0.f) ? v0 : 0.01f * v0;
                v1 = (v1 >= 0.f) ? v1 : 0.01f * v1;
                float p = v0 * v0 + v1 * v1;
                #pragma unroll
                for (int o = 16; o; o >>= 1) p += __shfl_xor_sync(0xffffffffu, p, o);
                float inv = 1.f / fmaxf(sqrtf(p), 1e-12f);
                if (row < N_NODES) {
                    *(float2*)(g_all + (size_t)row * ROWSTRIDE + (k + 1) * EMB + lane * 2)
                        = make_float2(v0, v1);
                    if (k < N_LAYERS - 1)
                        *(__nv_bfloat162*)(g_ego16 + (size_t)row * EMB + lane * 2)
                            = __floats2bfloat162_rn(v0, v1);
                    if (lane == 0) g_norm[(size_t)k * N_NODES + row] = inv;
                }
            }
        }
        __syncwarp();
    }
}

// ---------------------------------------------------------------------------
// BPR loss: one warp per batch element; also re-zeroes g_deg for next replay.
// ---------------------------------------------------------------------------
__global__ void loss_kernel(const int* __restrict__ u,
                            const int* __restrict__ ii,
                            const int* __restrict__ jj) {
    int t = blockIdx.x * 128 + threadIdx.x;               // 131072 threads
    if (t < N_NODES) g_deg[t] = 0;

    int warp = threadIdx.x >> 5, lane = threadIdx.x & 31;
    int b = blockIdx.x * 4 + warp;
    int un = u[b], pn = N_USERS + ii[b], nn = N_USERS + jj[b];
    const float* ur = g_all + (size_t)un * ROWSTRIDE;
    const float* pr = g_all + (size_t)pn * ROWSTRIDE;
    const float* nr = g_all + (size_t)nn * ROWSTRIDE;

    float iu[4], ip[4], in_[4];
    iu[0] = ip[0] = in_[0] = 1.f;
    #pragma unroll
    for (int s = 1; s < 4; s++) {
        iu[s]  = __ldg(&g_norm[(size_t)(s - 1) * N_NODES + un]);
        ip[s]  = __ldg(&g_norm[(size_t)(s - 1) * N_NODES + pn]);
        in_[s] = __ldg(&g_norm[(size_t)(s - 1) * N_NODES + nn]);
    }

    float dui = 0.f, duj = 0.f, l2 = 0.f;
    #pragma unroll
    for (int s = 0; s < 4; s++) {
        float2 uv = *(const float2*)(ur + s * EMB + lane * 2);
        float2 pv = *(const float2*)(pr + s * EMB + lane * 2);
        float2 nv = *(const float2*)(nr + s * EMB + lane * 2);
        uv.x *= iu[s];  uv.y *= iu[s];
        pv.x *= ip[s];  pv.y *= ip[s];
        nv.x *= in_[s]; nv.y *= in_[s];
        dui += uv.x * pv.x + uv.y * pv.y;
        duj += uv.x * nv.x + uv.y * nv.y;
        l2  += uv.x * uv.x + uv.y * uv.y
             + pv.x * pv.x + pv.y * pv.y
             + nv.x * nv.x + nv.y * nv.y;
    }
    #pragma unroll
    for (int o = 16; o; o >>= 1) {
        dui += __shfl_xor_sync(0xffffffffu, dui, o);
        duj += __shfl_xor_sync(0xffffffffu, duj, o);
        l2  += __shfl_xor_sync(0xffffffffu, l2,  o);
    }
    if (lane == 0) {
        float diff = dui - duj;
        float lp = fminf(diff, 0.f) - log1pf(expf(-fabsf(diff)));
        atomicAdd(&g_acc[0], lp);
        atomicAdd(&g_acc[1], 0.5f * l2);
    }
}

__global__ void finalize_kernel(float* out) {
    out[0] = -g_acc[0] / (float)BATCH + REG_L2 * (g_acc[1] / (float)BATCH);
    g_acc[0] = 0.f;
    g_acc[1] = 0.f;
}

// ---------------------------------------------------------------------------
extern "C" void kernel_launch(void* const* d_in, const int* in_sizes, int n_in,
                              void* d_out, int out_size) {
    const float* user_emb = (const float*)d_in[0];
    const float* item_emb = (const float*)d_in[1];
    const float* W_gc     = (const float*)d_in[2];
    const float* b_gc     = (const float*)d_in[3];
    const float* W_bi     = (const float*)d_in[4];
    const float* b_bi     = (const float*)d_in[5];
    const float* adj_val  = (const float*)d_in[6];
    const int*   adj_row  = (const int*)d_in[7];
    const int*   adj_col  = (const int*)d_in[8];
    const int*   u        = (const int*)d_in[9];
    const int*   i        = (const int*)d_in[10];
    const int*   j        = (const int*)d_in[11];
    float* out = (float*)d_out;

    static bool configured = false;
    if (!configured) {
        configured = true;
        cudaFuncSetAttribute(transform_kernel,
                             cudaFuncAttributeMaxDynamicSharedMemorySize, TR_SMEM);
    }

    init_kernel<<<(N_NODES * 16) / 256, 256>>>(user_emb, item_emb);
    scatter_kernel<<<(NNZ + 255) / 256, 256>>>(adj_row, adj_col, adj_val);

    for (int k = 0; k < N_LAYERS; k++) {
        spmm_kernel<<<(N_NODES * 32 + 255) / 256, 256>>>();
        transform_kernel<<<TR_GRID, 256, TR_SMEM>>>(W_gc, b_gc, W_bi, b_bi, k);
    }

    loss_kernel<<<BATCH / 4, 128>>>(u, i, j);
    finalize_kernel<<<1, 1>>>(out);
}

// round 11
// speedup vs baseline: 1.4570x; 1.3492x over previous
#include <cuda_runtime.h>
#include <cuda_bf16.h>

#define N_USERS 50000
#define N_ITEMS 50000
#define N_NODES 100000
#define NNZ     1600000
#define EMB     64
#define N_LAYERS 3
#define BATCH   4096
#define REG_L2  1e-5f

#define ROWSTRIDE (EMB * (N_LAYERS + 1))                 // 256
#define CAP 96          // padded edge slots per row (deg ~ Binom(1.6M,1e-5): mean 16, max ~40)

__device__ float g_all [(size_t)N_NODES * ROWSTRIDE];    // 102.4 MB
__device__ float g_side[(size_t)N_NODES * EMB];          // 25.6 MB
__device__ float g_norm[(size_t)N_LAYERS * N_NODES];     // 1.2 MB
__device__ float g_acc[2];                                // zero at load; re-zeroed by finalize
__device__ __nv_bfloat16 g_ego16[(size_t)N_NODES * EMB]; // 12.8 MB bf16 gather mirror

__device__ int  g_deg[N_NODES];                           // zero at load; re-zeroed by loss
__device__ int2 g_pad[(size_t)N_NODES * CAP];             // 76.8 MB {col, val bits}

__device__ __forceinline__ float4 bf16x4_to_f4(uint2 r) {
    __nv_bfloat162 lo = *(__nv_bfloat162*)&r.x;
    __nv_bfloat162 hi = *(__nv_bfloat162*)&r.y;
    float2 a = __bfloat1622float2(lo), b = __bfloat1622float2(hi);
    return make_float4(a.x, a.y, b.x, b.y);
}

// ---------------------------------------------------------------------------
__global__ void init_kernel(const float* __restrict__ ue, const float* __restrict__ ie) {
    int t = blockIdx.x * 256 + threadIdx.x;              // N_NODES*16 threads
    int node = t >> 4, q = t & 15;
    const float* src = (node < N_USERS) ? (ue + (size_t)node * EMB)
                                        : (ie + (size_t)(node - N_USERS) * EMB);
    float4 v = *(const float4*)(src + q * 4);
    *(float4*)(g_all + (size_t)node * ROWSTRIDE + q * 4) = v;
    __nv_bfloat162* b = (__nv_bfloat162*)(g_ego16 + (size_t)node * EMB + q * 4);
    b[0] = __floats2bfloat162_rn(v.x, v.y);
    b[1] = __floats2bfloat162_rn(v.z, v.w);
}

// ---------------------------------------------------------------------------
__global__ void scatter_kernel(const int* __restrict__ row,
                               const int* __restrict__ col,
                               const float* __restrict__ val) {
    int t = blockIdx.x * 256 + threadIdx.x;
    if (t >= NNZ) return;
    int r = __ldg(row + t);
    int slot = atomicAdd(&g_deg[r], 1);
    if (slot < CAP)
        g_pad[(size_t)r * CAP + slot] = make_int2(__ldg(col + t),
                                                  __float_as_int(__ldg(val + t)));
}

// ---------------------------------------------------------------------------
// SpMM: one warp per row, half-warp per edge, padded rows (proven config).
// ---------------------------------------------------------------------------
__global__ void __launch_bounds__(256) spmm_kernel() {
    int gt = blockIdx.x * 256 + threadIdx.x;
    int row = gt >> 5, lane = gt & 31;
    if (row >= N_NODES) return;
    int half = lane >> 4;
    int sub  = lane & 15;

    int deg = __ldg(&g_deg[row]);
    if (deg > CAP) deg = CAP;
    const int2* edges = g_pad + (size_t)row * CAP;
    float4 acc = make_float4(0.f, 0.f, 0.f, 0.f);

    int e = 0;
    for (; e + 8 <= deg; e += 8) {
        int2 c0 = __ldg(edges + e     + half);
        int2 c1 = __ldg(edges + e + 2 + half);
        int2 c2 = __ldg(edges + e + 4 + half);
        int2 c3 = __ldg(edges + e + 6 + half);
        uint2 r0 = __ldg((const uint2*)(g_ego16 + (size_t)c0.x * EMB) + sub);
        uint2 r1 = __ldg((const uint2*)(g_ego16 + (size_t)c1.x * EMB) + sub);
        uint2 r2 = __ldg((const uint2*)(g_ego16 + (size_t)c2.x * EMB) + sub);
        uint2 r3 = __ldg((const uint2*)(g_ego16 + (size_t)c3.x * EMB) + sub);
        float4 a0 = bf16x4_to_f4(r0), a1 = bf16x4_to_f4(r1);
        float4 a2 = bf16x4_to_f4(r2), a3 = bf16x4_to_f4(r3);
        float v0 = __int_as_float(c0.y), v1 = __int_as_float(c1.y);
        float v2 = __int_as_float(c2.y), v3 = __int_as_float(c3.y);
        acc.x += v0 * a0.x + v1 * a1.x + v2 * a2.x + v3 * a3.x;
        acc.y += v0 * a0.y + v1 * a1.y + v2 * a2.y + v3 * a3.y;
        acc.z += v0 * a0.z + v1 * a1.z + v2 * a2.z + v3 * a3.z;
        acc.w += v0 * a0.w + v1 * a1.w + v2 * a2.w + v3 * a3.w;
    }
    for (; e + 2 <= deg; e += 2) {
        int2 c = __ldg(edges + e + half);
        uint2 r = __ldg((const uint2*)(g_ego16 + (size_t)c.x * EMB) + sub);
        float4 a = bf16x4_to_f4(r);
        float v = __int_as_float(c.y);
        acc.x += v * a.x; acc.y += v * a.y; acc.z += v * a.z; acc.w += v * a.w;
    }
    if (e < deg && half == 0) {
        int2 c = __ldg(edges + e);
        uint2 r = __ldg((const uint2*)(g_ego16 + (size_t)c.x * EMB) + sub);
        float4 a = bf16x4_to_f4(r);
        float v = __int_as_float(c.y);
        acc.x += v * a.x; acc.y += v * a.y; acc.z += v * a.z; acc.w += v * a.w;
    }

    acc.x += __shfl_xor_sync(0xffffffffu, acc.x, 16);
    acc.y += __shfl_xor_sync(0xffffffffu, acc.y, 16);
    acc.z += __shfl_xor_sync(0xffffffffu, acc.z, 16);
    acc.w += __shfl_xor_sync(0xffffffffu, acc.w, 16);
    if (half == 0)
        *(float4*)(g_side + (size_t)row * EMB + sub * 4) = acc;
}

// ---------------------------------------------------------------------------
// Transform on TENSOR CORES (mma.sync m16n8k16 bf16 -> fp32):
//   C[16 x 64 per warp] = A[16 x 128] @ Wcat[128 x 64]
//   A = [x1 | x2] bf16 (per-warp smem tile), Wcat = [Wg ; Wb] bf16 (block smem)
// 8 warps * 16 rows = 128 rows/block.  N_NODES = 6250 * 16, so every live
// warp tile is full (no partial tiles).
// smem: W 128*72*2 = 18432 + bias 256 + A 8*16*136*2 = 34816  -> 53504 B
// Row paddings (+8 cols) make ldmatrix bank-conflict-free.
// ---------------------------------------------------------------------------
#define A_STRIDE 136
#define W_STRIDE 72
#define TR_SMEM (128 * W_STRIDE * 2 + 64 * 4 + 8 * 16 * A_STRIDE * 2)

__device__ __forceinline__ void ldsm_x4(unsigned& r0, unsigned& r1,
                                        unsigned& r2, unsigned& r3, unsigned addr) {
    asm volatile("ldmatrix.sync.aligned.m8n8.x4.shared.b16 {%0,%1,%2,%3}, [%4];"
                 : "=r"(r0), "=r"(r1), "=r"(r2), "=r"(r3) : "r"(addr));
}
__device__ __forceinline__ void ldsm_x2t(unsigned& r0, unsigned& r1, unsigned addr) {
    asm volatile("ldmatrix.sync.aligned.m8n8.x2.trans.shared.b16 {%0,%1}, [%2];"
                 : "=r"(r0), "=r"(r1) : "r"(addr));
}
#define MMA16816(c0,c1,c2,c3,a0,a1,a2,a3,b0,b1) \
    asm volatile("mma.sync.aligned.m16n8k16.row.col.f32.bf16.bf16.f32 " \
                 "{%0,%1,%2,%3}, {%4,%5,%6,%7}, {%8,%9}, {%0,%1,%2,%3};" \
                 : "+f"(c0), "+f"(c1), "+f"(c2), "+f"(c3) \
                 : "r"(a0), "r"(a1), "r"(a2), "r"(a3), "r"(b0), "r"(b1))

__global__ void __launch_bounds__(256) transform_kernel(
        const float* __restrict__ Wg, const float* __restrict__ bg,
        const float* __restrict__ Wb, const float* __restrict__ bb, int k) {
    extern __shared__ char sh[];
    __nv_bfloat16* shW = (__nv_bfloat16*)sh;                  // [in*72 + out]
    float*         shB = (float*)(sh + 128 * W_STRIDE * 2);   // 64 floats
    __nv_bfloat16* shA = (__nv_bfloat16*)(sh + 128 * W_STRIDE * 2 + 256);

    int tid = threadIdx.x;
    const float* Wg_k = Wg + k * 4096;
    const float* Wb_k = Wb + k * 4096;
    #pragma unroll
    for (int idx = tid; idx < 8192; idx += 256) {             // Wcat = [Wg; Wb]
        int in = idx >> 6, out = idx & 63;
        float w = (in < 64) ? __ldg(Wg_k + in * 64 + out)
                            : __ldg(Wb_k + (in - 64) * 64 + out);
        shW[in * W_STRIDE + out] = __float2bfloat16(w);
    }
    if (tid < 64) shB[tid] = bg[k * 64 + tid] + bb[k * 64 + tid];
    __syncthreads();

    int warp = tid >> 5, lane = tid & 31;
    int rowbase = blockIdx.x * 128 + warp * 16;
    if (rowbase >= N_NODES) return;                           // full tiles only

    __nv_bfloat16* A = shA + warp * 16 * A_STRIDE;
    const float* ego = g_all + k * EMB;

    // Stage A = [x1 | x2] in bf16; lane covers cols 2l, 2l+1 of each row.
    #pragma unroll 4
    for (int r = 0; r < 16; r++) {
        int row = rowbase + r;
        float2 s = *(const float2*)(g_side + (size_t)row * EMB + lane * 2);
        float2 e = *(const float2*)(ego + (size_t)row * ROWSTRIDE + lane * 2);
        float2 x2 = make_float2(e.x * (s.x - e.x), e.y * (s.y - e.y));
        *(__nv_bfloat162*)(A + r * A_STRIDE + 2 * lane)      = __floats2bfloat162_rn(s.x, s.y);
        *(__nv_bfloat162*)(A + r * A_STRIDE + 64 + 2 * lane) = __floats2bfloat162_rn(x2.x, x2.y);
    }
    __syncwarp();

    float acc[8][4];
    #pragma unroll
    for (int j = 0; j < 8; j++)
        #pragma unroll
        for (int c = 0; c < 4; c++) acc[j][c] = 0.f;

    unsigned aBase = (unsigned)__cvta_generic_to_shared(A)
                   + (lane & 15) * (A_STRIDE * 2) + (lane >> 4) * 16;
    unsigned bBase = (unsigned)__cvta_generic_to_shared(shW)
                   + (lane & 15) * (W_STRIDE * 2);

    #pragma unroll
    for (int s = 0; s < 8; s++) {                             // k-steps of 16
        unsigned a0, a1, a2, a3;
        ldsm_x4(a0, a1, a2, a3, aBase + s * 32);
        unsigned brow = bBase + s * 16 * (W_STRIDE * 2);
        #pragma unroll
        for (int j = 0; j < 8; j++) {                         // n-tiles of 8
            unsigned b0, b1;
            ldsm_x2t(b0, b1, brow + j * 16);
            MMA16816(acc[j][0], acc[j][1], acc[j][2], acc[j][3],
                     a0, a1, a2, a3, b0, b1);
        }
    }

    // Epilogue: +bias, leaky-relu, row norm (quad reduce), store.
    int q = lane & 3;
    int row_lo = rowbase + (lane >> 2), row_hi = row_lo + 8;
    float pl = 0.f, ph = 0.f;
    #pragma unroll
    for (int j = 0; j < 8; j++) {
        float b0 = shB[8 * j + 2 * q], b1 = shB[8 * j + 2 * q + 1];
        float v0 = acc[j][0] + b0, v1 = acc[j][1] + b1;
        float v2 = acc[j][2] + b0, v3 = acc[j][3] + b1;
        v0 = (v0 >= 0.f) ? v0 : 0.01f * v0;
        v1 = (v1 >= 0.f) ? v1 : 0.01f * v1;
        v2 = (v2 >= 0.f) ? v2 : 0.01f * v2;
        v3 = (v3 >= 0.f) ? v3 : 0.01f * v3;
        acc[j][0] = v0; acc[j][1] = v1; acc[j][2] = v2; acc[j][3] = v3;
        pl += v0 * v0 + v1 * v1;
        ph += v2 * v2 + v3 * v3;
    }
    pl += __shfl_xor_sync(0xffffffffu, pl, 1);
    pl += __shfl_xor_sync(0xffffffffu, pl, 2);
    ph += __shfl_xor_sync(0xffffffffu, ph, 1);
    ph += __shfl_xor_sync(0xffffffffu, ph, 2);
    if (q == 0) {
        g_norm[(size_t)k * N_NODES + row_lo] = 1.f / fmaxf(sqrtf(pl), 1e-12f);
        g_norm[(size_t)k * N_NODES + row_hi] = 1.f / fmaxf(sqrtf(ph), 1e-12f);
    }

    float* out_lo = g_all + (size_t)row_lo * ROWSTRIDE + (k + 1) * EMB;
    float* out_hi = g_all + (size_t)row_hi * ROWSTRIDE + (k + 1) * EMB;
    #pragma unroll
    for (int j = 0; j < 8; j++) {
        int col = 8 * j + 2 * q;
        *(float2*)(out_lo + col) = make_float2(acc[j][0], acc[j][1]);
        *(float2*)(out_hi + col) = make_float2(acc[j][2], acc[j][3]);
        if (k < N_LAYERS - 1) {
            *(__nv_bfloat162*)(g_ego16 + (size_t)row_lo * EMB + col)
                = __floats2bfloat162_rn(acc[j][0], acc[j][1]);
            *(__nv_bfloat162*)(g_ego16 + (size_t)row_hi * EMB + col)
                = __floats2bfloat162_rn(acc[j][2], acc[j][3]);
        }
    }
}

// ---------------------------------------------------------------------------
// BPR loss: one warp per batch element; also re-zeroes g_deg for next replay.
// ---------------------------------------------------------------------------
__global__ void loss_kernel(const int* __restrict__ u,
                            const int* __restrict__ ii,
                            const int* __restrict__ jj) {
    int t = blockIdx.x * 128 + threadIdx.x;               // 131072 threads
    if (t < N_NODES) g_deg[t] = 0;

    int warp = threadIdx.x >> 5, lane = threadIdx.x & 31;
    int b = blockIdx.x * 4 + warp;
    int un = u[b], pn = N_USERS + ii[b], nn = N_USERS + jj[b];
    const float* ur = g_all + (size_t)un * ROWSTRIDE;
    const float* pr = g_all + (size_t)pn * ROWSTRIDE;
    const float* nr = g_all + (size_t)nn * ROWSTRIDE;

    float iu[4], ip[4], in_[4];
    iu[0] = ip[0] = in_[0] = 1.f;
    #pragma unroll
    for (int s = 1; s < 4; s++) {
        iu[s]  = __ldg(&g_norm[(size_t)(s - 1) * N_NODES + un]);
        ip[s]  = __ldg(&g_norm[(size_t)(s - 1) * N_NODES + pn]);
        in_[s] = __ldg(&g_norm[(size_t)(s - 1) * N_NODES + nn]);
    }

    float dui = 0.f, duj = 0.f, l2 = 0.f;
    #pragma unroll
    for (int s = 0; s < 4; s++) {
        float2 uv = *(const float2*)(ur + s * EMB + lane * 2);
        float2 pv = *(const float2*)(pr + s * EMB + lane * 2);
        float2 nv = *(const float2*)(nr + s * EMB + lane * 2);
        uv.x *= iu[s];  uv.y *= iu[s];
        pv.x *= ip[s];  pv.y *= ip[s];
        nv.x *= in_[s]; nv.y *= in_[s];
        dui += uv.x * pv.x + uv.y * pv.y;
        duj += uv.x * nv.x + uv.y * nv.y;
        l2  += uv.x * uv.x + uv.y * uv.y
             + pv.x * pv.x + pv.y * pv.y
             + nv.x * nv.x + nv.y * nv.y;
    }
    #pragma unroll
    for (int o = 16; o; o >>= 1) {
        dui += __shfl_xor_sync(0xffffffffu, dui, o);
        duj += __shfl_xor_sync(0xffffffffu, duj, o);
        l2  += __shfl_xor_sync(0xffffffffu, l2,  o);
    }
    if (lane == 0) {
        float diff = dui - duj;
        float lp = fminf(diff, 0.f) - log1pf(expf(-fabsf(diff)));
        atomicAdd(&g_acc[0], lp);
        atomicAdd(&g_acc[1], 0.5f * l2);
    }
}

__global__ void finalize_kernel(float* out) {
    out[0] = -g_acc[0] / (float)BATCH + REG_L2 * (g_acc[1] / (float)BATCH);
    g_acc[0] = 0.f;
    g_acc[1] = 0.f;
}

// ---------------------------------------------------------------------------
extern "C" void kernel_launch(void* const* d_in, const int* in_sizes, int n_in,
                              void* d_out, int out_size) {
    const float* user_emb = (const float*)d_in[0];
    const float* item_emb = (const float*)d_in[1];
    const float* W_gc     = (const float*)d_in[2];
    const float* b_gc     = (const float*)d_in[3];
    const float* W_bi     = (const float*)d_in[4];
    const float* b_bi     = (const float*)d_in[5];
    const float* adj_val  = (const float*)d_in[6];
    const int*   adj_row  = (const int*)d_in[7];
    const int*   adj_col  = (const int*)d_in[8];
    const int*   u        = (const int*)d_in[9];
    const int*   i        = (const int*)d_in[10];
    const int*   j        = (const int*)d_in[11];
    float* out = (float*)d_out;

    static bool configured = false;
    if (!configured) {
        configured = true;
        cudaFuncSetAttribute(transform_kernel,
                             cudaFuncAttributeMaxDynamicSharedMemorySize, TR_SMEM);
    }

    init_kernel<<<(N_NODES * 16) / 256, 256>>>(user_emb, item_emb);
    scatter_kernel<<<(NNZ + 255) / 256, 256>>>(adj_row, adj_col, adj_val);

    for (int k = 0; k < N_LAYERS; k++) {
        spmm_kernel<<<(N_NODES * 32 + 255) / 256, 256>>>();
        transform_kernel<<<(N_NODES + 127) / 128, 256, TR_SMEM>>>(W_gc, b_gc, W_bi, b_bi, k);
    }

    loss_kernel<<<BATCH / 4, 128>>>(u, i, j);
    finalize_kernel<<<1, 1>>>(out);
}